// round 13
// baseline (speedup 1.0000x reference)
#include <cuda_runtime.h>

// Shapes (fixed by the problem)
#define NB   4096          // batch B
#define NP   12            // P = PATCH_NUM - MASK_NUM
#define DIN  640
#define DD   128
#define MP   (NP * NB)     // 49152
#define GBLK (NB / 128)    // 32 CTAs for the global input
#define PBLK (MP / 128)    // 384 CTAs for the patch input
#define INV_T    0.25f     // 1/T, T=4
#define KL_SCALE (16.0f / 128.0f)   // T^2 / D

// Packed-W sizes: [K/8 kb][2 part][8 jp][32 lane][4 w]
#define WF1_SZ ((DIN / 8) * 2 * 8 * 32 * 4)   // 163840
#define WF2_SZ ((DD  / 8) * 2 * 8 * 32 * 4)   // 32768

// Scratch (device globals: allocation-free rule)
__device__ float d_hg[NB * DD];
__device__ float d_hp[MP * DD];
__device__ float d_g[NB * DD];
__device__ float d_p[MP * DD];
__device__ float d_part_dil[NB];
__device__ float d_part_dcl[NB];
__device__ unsigned int d_ticket;   // zero-init; self-resets each launch
__device__ float d_wf1g[WF1_SZ];
__device__ float d_wf1p[WF1_SZ];
__device__ float d_wf2g[WF2_SZ];
__device__ float d_wf2p[WF2_SZ];

// ---------------------------------------------------------------------------
// TF32 helpers
// ---------------------------------------------------------------------------
__device__ __forceinline__ float tf32_rn(float v)
{
    unsigned r;
    asm("cvt.rna.tf32.f32 %0, %1;" : "=r"(r) : "f"(v));
    return __uint_as_float(r);
}

// mma.m16n8k8 tf32, explicit operands
#define MMA4(c, A0, A1, A2, A3, B0, B1)                                       \
    asm("mma.sync.aligned.m16n8k8.row.col.f32.tf32.tf32.f32 "                 \
        "{%0,%1,%2,%3}, {%4,%5,%6,%7}, {%8,%9}, {%0,%1,%2,%3};"               \
        : "+f"((c)[0]), "+f"((c)[1]), "+f"((c)[2]), "+f"((c)[3])              \
        : "r"(__float_as_uint(A0)), "r"(__float_as_uint(A1)),                 \
          "r"(__float_as_uint(A2)), "r"(__float_as_uint(A3)),                 \
          "r"(__float_as_uint(B0)), "r"(__float_as_uint(B1)))

// ---------------------------------------------------------------------------
// Pre-pack W: convert to tf32 hi/lo AND lay out in mma-fragment order.
// Output idx = ((((kb*2 + part)*8 + jp)*32 + lane)*4 + w):
//   ntile = 2*jp + (w>>1),  n = ntile*8 + (lane>>2)
//   k = kb*8 + (lane&3) + ((w&1) ? 4 : 0)
// ---------------------------------------------------------------------------
__global__ __launch_bounds__(256)
void pack_w_kernel(const float* __restrict__ W, float* __restrict__ Wf, int K)
{
    const int idx = blockIdx.x * blockDim.x + threadIdx.x;
    const int w    = idx & 3;
    const int l    = (idx >> 2) & 31;
    const int jp   = (idx >> 7) & 7;
    const int part = (idx >> 10) & 1;
    const int kb   = idx >> 11;
    if (kb >= K / 8) return;
    const int n = (2 * jp + (w >> 1)) * 8 + (l >> 2);
    const int k = kb * 8 + (l & 3) + ((w & 1) ? 4 : 0);
    const float v = W[n * K + k];
    const float h = tf32_rn(v);
    Wf[idx] = part ? tf32_rn(v - h) : h;
}

// ---------------------------------------------------------------------------
// Fused-grid TF32 GEMM (3xTF32) with fragment-ready W and permuted-k A smem.
// BM=128, BN=128, BK=16, 256 threads = 8 warps (4 m x 2 n),
// warp tile 32x64. A: hi/lo smem, k-permuted so fragment pairs are LDS.64.
// W: preconverted fragment-order gmem -> vector copy -> LDS.128 fragments.
// ---------------------------------------------------------------------------
template <bool RELU>
__global__ __launch_bounds__(256, 2)
void mlp_gemm(const float* __restrict__ Ag, const float* __restrict__ Ap,
              const float* __restrict__ Wfg, const float* __restrict__ bg,
              const float* __restrict__ Wfp, const float* __restrict__ bp,
              float* __restrict__ outg, float* __restrict__ outp, int K)
{
    const float* A; const float* Wf; const float* bias; float* out; int m0;
    if (blockIdx.x < GBLK) {
        A = Ag; Wf = Wfg; bias = bg; out = outg; m0 = blockIdx.x * 128;
    } else {
        A = Ap; Wf = Wfp; bias = bp; out = outp; m0 = (blockIdx.x - GBLK) * 128;
    }

    __shared__ float Ah[128][20];   // [m][perm-k], pad to 20
    __shared__ float Al[128][20];
    __shared__ float4 Wsm4[1024];   // 16KB: [kb2][part][jp8][lane32][w4]
    float* Wsm = (float*)Wsm4;

    const int tid    = threadIdx.x;
    const int lane   = tid & 31;
    const int wid    = tid >> 5;
    const int warp_m = wid & 3;
    const int warp_n = wid >> 2;
    const int gid    = lane >> 2;
    const int tq     = lane & 3;

    const int lrow = tid >> 2;      // 0..63
    const int kq   = tid & 3;

    const float* Ar0 = A + (m0 + lrow) * K;
    const float* Ar1 = A + (m0 + lrow + 64) * K;
    const float4* Wf4 = (const float4*)Wf;

    float acc[2][8][4];
#pragma unroll
    for (int i = 0; i < 2; i++)
#pragma unroll
        for (int j = 0; j < 8; j++)
#pragma unroll
            for (int q = 0; q < 4; q++) acc[i][j][q] = 0.0f;

    // prefetch stage 0
    float pa[8];
    float4 wv[4];
#pragma unroll
    for (int j = 0; j < 4; j++) {
        pa[j]     = Ar0[kq + 4 * j];
        pa[4 + j] = Ar1[kq + 4 * j];
    }
#pragma unroll
    for (int i = 0; i < 4; i++) wv[i] = Wf4[tid + 256 * i];

    const int NS = K / 16;
    for (int s = 0; s < NS; s++) {
        __syncthreads();
        // ---- A store: hi/lo split into permuted-k positions ----
#pragma unroll
        for (int half = 0; half < 2; half++) {
            const int r = lrow + half * 64;
            const float* v = pa + half * 4;
            float h0 = tf32_rn(v[0]), h1 = tf32_rn(v[1]);
            float h2 = tf32_rn(v[2]), h3 = tf32_rn(v[3]);
            *(float2*)&Ah[r][2 * kq]     = make_float2(h0, h1); // k=kq, kq+4
            *(float2*)&Ah[r][8 + 2 * kq] = make_float2(h2, h3); // k=kq+8, kq+12
            *(float2*)&Al[r][2 * kq]     = make_float2(tf32_rn(v[0] - h0),
                                                       tf32_rn(v[1] - h1));
            *(float2*)&Al[r][8 + 2 * kq] = make_float2(tf32_rn(v[2] - h2),
                                                       tf32_rn(v[3] - h3));
        }
        // ---- W store: straight vector copy ----
#pragma unroll
        for (int i = 0; i < 4; i++) Wsm4[tid + 256 * i] = wv[i];
        __syncthreads();

        // prefetch next stage
        if (s + 1 < NS) {
            const int kt = (s + 1) * 16;
#pragma unroll
            for (int j = 0; j < 4; j++) {
                pa[j]     = Ar0[kt + kq + 4 * j];
                pa[4 + j] = Ar1[kt + kq + 4 * j];
            }
#pragma unroll
            for (int i = 0; i < 4; i++)
                wv[i] = Wf4[(s + 1) * 1024 + tid + 256 * i];
        }

        // ---- compute: 2 k8 steps ----
#pragma unroll
        for (int kb = 0; kb < 2; kb++) {
            // A fragments: (a0,a2) and (a1,a3) each via one LDS.64
            float2 ah0[2], ah1[2], al0[2], al1[2];
#pragma unroll
            for (int mt = 0; mt < 2; mt++) {
                const int r = warp_m * 32 + mt * 16;
                ah0[mt] = *(const float2*)&Ah[r + gid]    [kb * 8 + 2 * tq];
                ah1[mt] = *(const float2*)&Ah[r + gid + 8][kb * 8 + 2 * tq];
                al0[mt] = *(const float2*)&Al[r + gid]    [kb * 8 + 2 * tq];
                al1[mt] = *(const float2*)&Al[r + gid + 8][kb * 8 + 2 * tq];
            }
#pragma unroll
            for (int jpl = 0; jpl < 4; jpl++) {
                const int jp = warp_n * 4 + jpl;
                const float4 bh = *(const float4*)
                    &Wsm[((kb * 2 + 0) * 8 + jp) * 128 + lane * 4];
                const float4 bl = *(const float4*)
                    &Wsm[((kb * 2 + 1) * 8 + jp) * 128 + lane * 4];
#pragma unroll
                for (int mt = 0; mt < 2; mt++) {
                    const int nt0 = 2 * jpl;
                    // pass 1: hi * hi
                    MMA4(acc[mt][nt0],     ah0[mt].x, ah1[mt].x, ah0[mt].y, ah1[mt].y, bh.x, bh.y);
                    MMA4(acc[mt][nt0 + 1], ah0[mt].x, ah1[mt].x, ah0[mt].y, ah1[mt].y, bh.z, bh.w);
                    // pass 2: lo * hi
                    MMA4(acc[mt][nt0],     al0[mt].x, al1[mt].x, al0[mt].y, al1[mt].y, bh.x, bh.y);
                    MMA4(acc[mt][nt0 + 1], al0[mt].x, al1[mt].x, al0[mt].y, al1[mt].y, bh.z, bh.w);
                    // pass 3: hi * lo
                    MMA4(acc[mt][nt0],     ah0[mt].x, ah1[mt].x, ah0[mt].y, ah1[mt].y, bl.x, bl.y);
                    MMA4(acc[mt][nt0 + 1], ah0[mt].x, ah1[mt].x, ah0[mt].y, ah1[mt].y, bl.z, bl.w);
                }
            }
        }
    }

    // -------------------------- epilogue -----------------------------------
    float2 bb[8];
#pragma unroll
    for (int nt = 0; nt < 8; nt++)
        bb[nt] = *(const float2*)&bias[warp_n * 64 + nt * 8 + tq * 2];

    if (RELU) {
#pragma unroll
        for (int mt = 0; mt < 2; mt++) {
            const int r0 = m0 + warp_m * 32 + mt * 16 + gid;
#pragma unroll
            for (int nt = 0; nt < 8; nt++) {
                const int col = warp_n * 64 + nt * 8 + tq * 2;
                float2 v0, v1;
                v0.x = fmaxf(acc[mt][nt][0] + bb[nt].x, 0.0f);
                v0.y = fmaxf(acc[mt][nt][1] + bb[nt].y, 0.0f);
                v1.x = fmaxf(acc[mt][nt][2] + bb[nt].x, 0.0f);
                v1.y = fmaxf(acc[mt][nt][3] + bb[nt].y, 0.0f);
                *(float2*)(out + r0 * DD + col)       = v0;
                *(float2*)(out + (r0 + 8) * DD + col) = v1;
            }
        }
    } else {
#pragma unroll
        for (int mt = 0; mt < 2; mt++)
#pragma unroll
            for (int nt = 0; nt < 8; nt++) {
                acc[mt][nt][0] += bb[nt].x;
                acc[mt][nt][1] += bb[nt].y;
                acc[mt][nt][2] += bb[nt].x;
                acc[mt][nt][3] += bb[nt].y;
            }

        float s0[2], s1[2];
#pragma unroll
        for (int mt = 0; mt < 2; mt++) {
            float a = 0.0f, c = 0.0f;
#pragma unroll
            for (int nt = 0; nt < 8; nt++) {
                a = fmaf(acc[mt][nt][0], acc[mt][nt][0], a);
                a = fmaf(acc[mt][nt][1], acc[mt][nt][1], a);
                c = fmaf(acc[mt][nt][2], acc[mt][nt][2], c);
                c = fmaf(acc[mt][nt][3], acc[mt][nt][3], c);
            }
            s0[mt] = a; s1[mt] = c;
        }
#pragma unroll
        for (int o = 1; o < 4; o <<= 1) {
#pragma unroll
            for (int mt = 0; mt < 2; mt++) {
                s0[mt] += __shfl_xor_sync(0xffffffffu, s0[mt], o);
                s1[mt] += __shfl_xor_sync(0xffffffffu, s1[mt], o);
            }
        }
        float* rsbuf = &Ah[0][0];   // 256 floats reused
        __syncthreads();
        if (tq == 0) {
#pragma unroll
            for (int mt = 0; mt < 2; mt++) {
                const int lr0 = warp_m * 32 + mt * 16 + gid;
                rsbuf[lr0 * 2 + warp_n]       = s0[mt];
                rsbuf[(lr0 + 8) * 2 + warp_n] = s1[mt];
            }
        }
        __syncthreads();
#pragma unroll
        for (int mt = 0; mt < 2; mt++) {
            const int lr0 = warp_m * 32 + mt * 16 + gid;
            const float inv0 = rsqrtf(rsbuf[lr0 * 2] + rsbuf[lr0 * 2 + 1]);
            const float inv1 = rsqrtf(rsbuf[(lr0 + 8) * 2] + rsbuf[(lr0 + 8) * 2 + 1]);
            const int r0 = m0 + lr0;
#pragma unroll
            for (int nt = 0; nt < 8; nt++) {
                const int col = warp_n * 64 + nt * 8 + tq * 2;
                float2 v0, v1;
                v0.x = acc[mt][nt][0] * inv0;
                v0.y = acc[mt][nt][1] * inv0;
                v1.x = acc[mt][nt][2] * inv1;
                v1.y = acc[mt][nt][3] * inv1;
                *(float2*)(out + r0 * DD + col)       = v0;
                *(float2*)(out + (r0 + 8) * DD + col) = v1;
            }
        }
    }
}

// ---------------------------------------------------------------------------
// Symmetric KL over one D=128 row handled by one warp (4 elems / lane).
// ---------------------------------------------------------------------------
__device__ __forceinline__ float warp_sum(float v)
{
#pragma unroll
    for (int o = 16; o > 0; o >>= 1) v += __shfl_xor_sync(0xffffffffu, v, o);
    return v;
}
__device__ __forceinline__ float warp_max(float v)
{
#pragma unroll
    for (int o = 16; o > 0; o >>= 1)
        v = fmaxf(v, __shfl_xor_sync(0xffffffffu, v, o));
    return v;
}

__device__ __forceinline__ float sym_kl(const float z1[4], const float z2[4])
{
    float m1 = fmaxf(fmaxf(z1[0], z1[1]), fmaxf(z1[2], z1[3]));
    float m2 = fmaxf(fmaxf(z2[0], z2[1]), fmaxf(z2[2], z2[3]));
    m1 = warp_max(m1);
    m2 = warp_max(m2);
    float e1[4], e2[4], s1 = 0.0f, s2 = 0.0f;
#pragma unroll
    for (int i = 0; i < 4; i++) {
        e1[i] = __expf(z1[i] - m1); s1 += e1[i];
        e2[i] = __expf(z2[i] - m2); s2 += e2[i];
    }
    s1 = warp_sum(s1);
    s2 = warp_sum(s2);
    const float inv1 = 1.0f / s1, inv2 = 1.0f / s2;
    const float c1 = m1 + __logf(s1), c2 = m2 + __logf(s2);
    float c = 0.0f;
#pragma unroll
    for (int i = 0; i < 4; i++) {
        const float l1 = z1[i] - c1;
        const float l2 = z2[i] - c2;
        c += (e1[i] * inv1 - e2[i] * inv2) * (l1 - l2);
    }
    return warp_sum(c);
}

// ---------------------------------------------------------------------------
// Fused loss: one block per b (128 threads = 4 warps). Last block reduces.
// ---------------------------------------------------------------------------
__global__ __launch_bounds__(128) void loss_kernel(float* __restrict__ out)
{
    __shared__ float sp[NP][DD];
    __shared__ float sg[DD];
    __shared__ float spb[DD];
    __shared__ float wpart[4];
    __shared__ int   amLast;

    const int b    = blockIdx.x;
    const int tid  = threadIdx.x;
    const int w    = tid >> 5;
    const int lane = tid & 31;

    sg[tid] = d_g[b * DD + tid];
    float s = 0.0f;
#pragma unroll
    for (int l = 0; l < NP; l++) {
        const float pv = d_p[(l * NB + b) * DD + tid];
        sp[l][tid] = pv;
        s += pv;
    }
    spb[tid] = s * (1.0f / 12.0f);
    __syncthreads();

    float gv[4], pbv[4];
#pragma unroll
    for (int i = 0; i < 4; i++) {
        gv[i]  = sg[lane + 32 * i];
        pbv[i] = spb[lane + 32 * i];
    }

    float dcl = 0.0f;
#pragma unroll
    for (int t = 0; t < 3; t++) {
        const int l = w * 3 + t;
        float z1[4], z2[4];
#pragma unroll
        for (int i = 0; i < 4; i++) {
            const float pv = sp[l][lane + 32 * i];
            const float t1 = gv[i] - pv;
            const float t2 = pbv[i] - pv;
            z1[i] = t1 * t1 * INV_T;
            z2[i] = t2 * t2 * INV_T;
        }
        dcl += sym_kl(z1, z2);
    }
    if (lane == 0) wpart[w] = dcl * KL_SCALE;

    if (w == 0) {
        float z1[4], z2[4];
#pragma unroll
        for (int i = 0; i < 4; i++) {
            z1[i] = gv[i] * INV_T;
            z2[i] = pbv[i] * INV_T;
        }
        const float dil = sym_kl(z1, z2) * KL_SCALE;
        if (lane == 0) d_part_dil[b] = dil;
    }
    __syncthreads();

    if (tid == 0) {
        d_part_dcl[b] = wpart[0] + wpart[1] + wpart[2] + wpart[3];
        __threadfence();
        amLast = (atomicAdd(&d_ticket, 1u) == (unsigned)(NB - 1));
    }
    __syncthreads();

    if (amLast) {
        __shared__ float r1[128], r2[128];
        float a = 0.0f, c = 0.0f;
        for (int i = tid; i < NB; i += 128) {
            a += d_part_dil[i];
            c += d_part_dcl[i];
        }
        r1[tid] = a; r2[tid] = c;
        __syncthreads();
        for (int o = 64; o > 0; o >>= 1) {
            if (tid < o) { r1[tid] += r1[tid + o]; r2[tid] += r2[tid + o]; }
            __syncthreads();
        }
        if (tid == 0) {
            out[0] = r1[0];
            out[1] = r2[0] * (1.0f / 12.0f);
            d_ticket = 0;
        }
    }
}

// ---------------------------------------------------------------------------
// Launch
// Inputs: ebg, ebp, labelsg, glo_w1, glo_b1, glo_w2, glo_b2,
//         pat_w1, pat_b1, pat_w2, pat_b2
// ---------------------------------------------------------------------------
extern "C" void kernel_launch(void* const* d_in, const int* in_sizes, int n_in,
                              void* d_out, int out_size)
{
    const float* ebg    = (const float*)d_in[0];
    const float* ebp    = (const float*)d_in[1];
    const float* glo_w1 = (const float*)d_in[3];
    const float* glo_b1 = (const float*)d_in[4];
    const float* glo_w2 = (const float*)d_in[5];
    const float* glo_b2 = (const float*)d_in[6];
    const float* pat_w1 = (const float*)d_in[7];
    const float* pat_b1 = (const float*)d_in[8];
    const float* pat_w2 = (const float*)d_in[9];
    const float* pat_b2 = (const float*)d_in[10];
    float* out = (float*)d_out;

    float *hg, *hp, *g, *p, *wf1g, *wf1p, *wf2g, *wf2p;
    cudaGetSymbolAddress((void**)&hg,   d_hg);
    cudaGetSymbolAddress((void**)&hp,   d_hp);
    cudaGetSymbolAddress((void**)&g,    d_g);
    cudaGetSymbolAddress((void**)&p,    d_p);
    cudaGetSymbolAddress((void**)&wf1g, d_wf1g);
    cudaGetSymbolAddress((void**)&wf1p, d_wf1p);
    cudaGetSymbolAddress((void**)&wf2g, d_wf2g);
    cudaGetSymbolAddress((void**)&wf2p, d_wf2p);

    // Pre-pack weights (fragment-order tf32 hi/lo)
    pack_w_kernel<<<WF1_SZ / 256, 256>>>(glo_w1, wf1g, DIN);
    pack_w_kernel<<<WF1_SZ / 256, 256>>>(pat_w1, wf1p, DIN);
    pack_w_kernel<<<WF2_SZ / 256, 256>>>(glo_w2, wf2g, DD);
    pack_w_kernel<<<WF2_SZ / 256, 256>>>(pat_w2, wf2p, DD);

    // Layer 1 (K=640) + ReLU — one grid covers global (32) + patch (384)
    mlp_gemm<true><<<GBLK + PBLK, 256>>>(ebg, ebp, wf1g, glo_b1,
                                         wf1p, pat_b1, hg, hp, DIN);
    // Layer 2 (K=128) + bias + L2 normalize
    mlp_gemm<false><<<GBLK + PBLK, 256>>>(hg, hp, wf2g, glo_b2,
                                          wf2p, pat_b2, g, p, DD);
    // Fused pbar + dil + dcl + final reduction (last block)
    loss_kernel<<<NB, 128>>>(out);
}